// round 7
// baseline (speedup 1.0000x reference)
#include <cuda_runtime.h>

#define IN_DIM 128
#define OUT_DIM 32
#define NMAX 100000
#define CAP 64            // bin capacity per node; Poisson(16) tail => overflow ~never

__device__ float  g_z[NMAX * OUT_DIM];     // z = h @ W_fc
__device__ float  g_el[NMAX];              // z @ a_l
__device__ float  g_er[NMAX];              // z @ a_r
__device__ int    g_count[NMAX];           // edges binned per dst
__device__ float2 g_bin[NMAX * CAP];       // (src_as_float_bits, p) per edge
__device__ float  g_esum[NMAX];            // fallback-only esum
__device__ float  g_hacc[NMAX * OUT_DIM];  // fallback contributions, then h_out
__device__ float  g_stats[2 * OUT_DIM];    // channel sum, sumsq

// ---------------------------------------------------------------------------
// K1: zero accumulators (store pipe idle during GEMM),
// then z = h @ W_fc ; el = z@a_l ; er = z@a_r   (warp: 4 nodes, lane = col)
// ---------------------------------------------------------------------------
__global__ void __launch_bounds__(256) k_gemm(
    const float* __restrict__ h, const float* __restrict__ Wfc,
    const float* __restrict__ Wa, int n)
{
    __shared__ float Ws[IN_DIM * OUT_DIM];        // 16 KB
    __shared__ float4 hs4[8][4 * 32];             // 16 KB

    {
        const int tid = blockIdx.x * blockDim.x + threadIdx.x;
        const int gs  = gridDim.x * blockDim.x;
        float4 z4 = make_float4(0.f, 0.f, 0.f, 0.f);
        float4* hacc4 = reinterpret_cast<float4*>(g_hacc);
        const int total4 = n * (OUT_DIM / 4);
        for (int i = tid; i < total4; i += gs) hacc4[i] = z4;
        for (int i = tid; i < n; i += gs) { g_esum[i] = 0.0f; g_count[i] = 0; }
        if (tid < 2 * OUT_DIM) g_stats[tid] = 0.0f;
    }

    for (int i = threadIdx.x; i < IN_DIM * OUT_DIM; i += blockDim.x)
        Ws[i] = Wfc[i];
    __syncthreads();

    const int lane = threadIdx.x & 31;
    const int wid  = threadIdx.x >> 5;
    const int gw   = (blockIdx.x * blockDim.x + threadIdx.x) >> 5;
    const int nw   = (gridDim.x * blockDim.x) >> 5;

    const float al = Wa[lane];
    const float ar = Wa[OUT_DIM + lane];
    float4* hsw = hs4[wid];

    const int ngroups = (n + 3) >> 2;
    for (int g = gw; g < ngroups; g += nw) {
        const int base = g * 4;
        #pragma unroll
        for (int i = 0; i < 4; i++) {
            int node = base + i;
            if (node < n)
                hsw[i * 32 + lane] =
                    reinterpret_cast<const float4*>(h + (size_t)node * IN_DIM)[lane];
        }
        __syncwarp();

        float acc0 = 0.f, acc1 = 0.f, acc2 = 0.f, acc3 = 0.f;
        #pragma unroll 8
        for (int k4 = 0; k4 < 32; k4++) {
            const float w0 = Ws[(k4 * 4 + 0) * 32 + lane];
            const float w1 = Ws[(k4 * 4 + 1) * 32 + lane];
            const float w2 = Ws[(k4 * 4 + 2) * 32 + lane];
            const float w3 = Ws[(k4 * 4 + 3) * 32 + lane];
            const float4 h0 = hsw[0 * 32 + k4];
            const float4 h1 = hsw[1 * 32 + k4];
            const float4 h2 = hsw[2 * 32 + k4];
            const float4 h3 = hsw[3 * 32 + k4];
            acc0 = fmaf(h0.x, w0, acc0); acc0 = fmaf(h0.y, w1, acc0);
            acc0 = fmaf(h0.z, w2, acc0); acc0 = fmaf(h0.w, w3, acc0);
            acc1 = fmaf(h1.x, w0, acc1); acc1 = fmaf(h1.y, w1, acc1);
            acc1 = fmaf(h1.z, w2, acc1); acc1 = fmaf(h1.w, w3, acc1);
            acc2 = fmaf(h2.x, w0, acc2); acc2 = fmaf(h2.y, w1, acc2);
            acc2 = fmaf(h2.z, w2, acc2); acc2 = fmaf(h2.w, w3, acc2);
            acc3 = fmaf(h3.x, w0, acc3); acc3 = fmaf(h3.y, w1, acc3);
            acc3 = fmaf(h3.z, w2, acc3); acc3 = fmaf(h3.w, w3, acc3);
        }

        float zz[4] = {acc0, acc1, acc2, acc3};
        #pragma unroll
        for (int i = 0; i < 4; i++) {
            int node = base + i;
            if (node >= n) break;
            float z = zz[i];
            g_z[node * OUT_DIM + lane] = z;
            float vl = z * al;
            float vr = z * ar;
            #pragma unroll
            for (int off = 16; off; off >>= 1) {
                vl += __shfl_xor_sync(0xffffffffu, vl, off);
                vr += __shfl_xor_sync(0xffffffffu, vr, off);
            }
            if (lane == 0) { g_el[node] = vl; g_er[node] = vr; }
        }
        __syncwarp();
    }
}

// ---------------------------------------------------------------------------
// K2: scatter pass, thread-per-edge. One exp per edge. Bins (src, p) by dst.
// Rare bin overflow falls back to fp atomics (exact correctness).
// ---------------------------------------------------------------------------
__global__ void __launch_bounds__(256) k_scatter(
    const int* __restrict__ src, const int* __restrict__ dst, int nedges)
{
    const int tid = blockIdx.x * blockDim.x + threadIdx.x;
    const int gs  = gridDim.x * blockDim.x;
    for (int e = tid; e < nedges; e += gs) {
        const int s = __ldg(&src[e]);
        const int d = __ldg(&dst[e]);
        float ee = __ldg(&g_el[s]) + __ldg(&g_er[d]);
        ee = (ee >= 0.0f) ? ee : 0.01f * ee;
        const float p = __expf(ee);
        const int pos = atomicAdd(&g_count[d], 1);
        if (pos < CAP) {
            g_bin[d * CAP + pos] = make_float2(__int_as_float(s), p);
        } else {
            atomicAdd(&g_esum[d], p);
            const float* zrow = g_z + s * OUT_DIM;
            float* hrow = g_hacc + d * OUT_DIM;
            #pragma unroll
            for (int c = 0; c < OUT_DIM; c++)
                atomicAdd(&hrow[c], p * __ldg(&zrow[c]));
        }
    }
}

// ---------------------------------------------------------------------------
// K3: aggregate, warp-per-node, lane = channel. Register accumulation,
// in-register softmax normalization, fused BN stats. Writes h_out into g_hacc.
// ---------------------------------------------------------------------------
__global__ void __launch_bounds__(256) k_aggr(int n)
{
    __shared__ float redbuf[2][8][32];
    const int lane = threadIdx.x & 31;
    const int wid  = threadIdx.x >> 5;
    const int gw   = (blockIdx.x * blockDim.x + threadIdx.x) >> 5;
    const int nw   = (gridDim.x * blockDim.x) >> 5;

    float s = 0.f, sq = 0.f;
    for (int nd = gw; nd < n; nd += nw) {
        const int cnt = g_count[nd];
        const int deg = (cnt < CAP) ? cnt : CAP;
        float acc = g_hacc[nd * OUT_DIM + lane];   // fallback contributions (usually 0)
        float es  = g_esum[nd];                    // fallback esum (usually 0)

        for (int base = 0; base < deg; base += 32) {
            const int m = (deg - base < 32) ? (deg - base) : 32;
            float2 entry = make_float2(0.f, 0.f);
            if (lane < m) entry = g_bin[nd * CAP + base + lane];

            int j = 0;
            for (; j + 1 < m; j += 2) {
                const float p0 = __shfl_sync(0xffffffffu, entry.y, j);
                const int   s0 = __shfl_sync(0xffffffffu, __float_as_int(entry.x), j);
                const float p1 = __shfl_sync(0xffffffffu, entry.y, j + 1);
                const int   s1 = __shfl_sync(0xffffffffu, __float_as_int(entry.x), j + 1);
                const float z0 = __ldg(&g_z[s0 * OUT_DIM + lane]);
                const float z1 = __ldg(&g_z[s1 * OUT_DIM + lane]);
                acc = fmaf(p0, z0, acc);
                acc = fmaf(p1, z1, acc);
                es += p0 + p1;
            }
            if (j < m) {
                const float p0 = __shfl_sync(0xffffffffu, entry.y, j);
                const int   s0 = __shfl_sync(0xffffffffu, __float_as_int(entry.x), j);
                acc = fmaf(p0, __ldg(&g_z[s0 * OUT_DIM + lane]), acc);
                es += p0;
            }
        }

        const float inv = (es > 0.0f) ? __frcp_rn(es) : 0.0f;
        const float v = acc * inv;
        g_hacc[nd * OUT_DIM + lane] = v;           // h_out (pre-BN)
        s += v;
        sq = fmaf(v, v, sq);
    }
    redbuf[0][wid][lane] = s;
    redbuf[1][wid][lane] = sq;
    __syncthreads();
    if (wid == 0) {
        float a = 0.f, b = 0.f;
        #pragma unroll
        for (int w = 0; w < 8; w++) { a += redbuf[0][w][lane]; b += redbuf[1][w][lane]; }
        atomicAdd(&g_stats[lane], a);
        atomicAdd(&g_stats[OUT_DIM + lane], b);
    }
}

// ---------------------------------------------------------------------------
// K4: BN affine + ELU, pure float4 map.
// ---------------------------------------------------------------------------
__global__ void __launch_bounds__(256) k_elu(float* __restrict__ out,
                                             const float* __restrict__ gamma,
                                             const float* __restrict__ beta, int n)
{
    __shared__ float sc_s[OUT_DIM], sh_s[OUT_DIM];
    if (threadIdx.x < OUT_DIM) {
        const int t = threadIdx.x;
        const float inv_n = 1.0f / (float)n;
        const float mean = g_stats[t] * inv_n;
        const float var  = g_stats[OUT_DIM + t] * inv_n - mean * mean;
        const float sc   = gamma[t] * rsqrtf(var + 1e-5f);
        sc_s[t] = sc;
        sh_s[t] = beta[t] - mean * sc;
    }
    __syncthreads();

    const int q = threadIdx.x & 7;              // float4 quarter of the 32 channels
    const float4 sc = reinterpret_cast<const float4*>(sc_s)[q];
    const float4 sh = reinterpret_cast<const float4*>(sh_s)[q];
    const int total4 = n * (OUT_DIM / 4);
    const int stride = gridDim.x * blockDim.x;
    const float4* hacc4 = reinterpret_cast<const float4*>(g_hacc);
    float4* out4 = reinterpret_cast<float4*>(out);

    for (int i = blockIdx.x * blockDim.x + threadIdx.x; i < total4; i += stride) {
        float4 v = hacc4[i];
        v.x = fmaf(v.x, sc.x, sh.x);
        v.y = fmaf(v.y, sc.y, sh.y);
        v.z = fmaf(v.z, sc.z, sh.z);
        v.w = fmaf(v.w, sc.w, sh.w);
        v.x = (v.x > 0.f) ? v.x : expm1f(v.x);
        v.y = (v.y > 0.f) ? v.y : expm1f(v.y);
        v.z = (v.z > 0.f) ? v.z : expm1f(v.z);
        v.w = (v.w > 0.f) ? v.w : expm1f(v.w);
        out4[i] = v;
    }
}

// ---------------------------------------------------------------------------
extern "C" void kernel_launch(void* const* d_in, const int* in_sizes, int n_in,
                              void* d_out, int out_size)
{
    const float* h     = (const float*)d_in[0];
    const float* Wfc   = (const float*)d_in[1];
    const float* Wa    = (const float*)d_in[2];
    const float* gamma = (const float*)d_in[3];
    const float* beta  = (const float*)d_in[4];
    const int*   src   = (const int*)d_in[5];
    const int*   dst   = (const int*)d_in[6];

    const int n      = in_sizes[0] / IN_DIM;   // 100000
    const int nedges = in_sizes[5];            // 1600000
    float* out = (float*)d_out;

    k_gemm   <<<1480, 256>>>(h, Wfc, Wa, n);
    k_scatter<<<3125, 256>>>(src, dst, nedges);
    k_aggr   <<<2048, 256>>>(n);
    k_elu    <<<512, 256>>>(out, gamma, beta, n);
}

// round 8
// speedup vs baseline: 1.0339x; 1.0339x over previous
#include <cuda_runtime.h>
#include <cuda_fp16.h>

#define IN_DIM 128
#define OUT_DIM 32
#define NMAX 100000

__device__ __half g_zh[NMAX * OUT_DIM];    // z in fp16 (edge gather payload only)
__device__ float g_el[NMAX];               // z @ a_l  (fp32, from fp32 z)
__device__ float g_er[NMAX];               // z @ a_r
__device__ float g_esum[NMAX];             // sum exp(e) per dst
__device__ float g_hacc[NMAX * OUT_DIM];   // sum exp(e)*z[src] per dst (fp32 accum)
__device__ float g_stats[2 * OUT_DIM];     // channel sum, sumsq

__device__ __forceinline__ void red_add_v4(float* addr, float4 v) {
    asm volatile("red.global.add.v4.f32 [%0], {%1,%2,%3,%4};"
                 :: "l"(addr), "f"(v.x), "f"(v.y), "f"(v.z), "f"(v.w)
                 : "memory");
}

// ---------------------------------------------------------------------------
// K1: zero accumulators (store pipe idle during GEMM), then
// z = h @ W_fc (fp32 math, fp16 store) ; el = z@a_l ; er = z@a_r
// W held transposed+padded in smem -> one LDS.128 per k4 step.
// ---------------------------------------------------------------------------
#define WT_PITCH 132   // 128 + 4 pad floats; 528B rows keep 16B alignment, spread banks

__global__ void __launch_bounds__(256) k_gemm(
    const float* __restrict__ h, const float* __restrict__ Wfc,
    const float* __restrict__ Wa, int n)
{
    __shared__ float Wt[OUT_DIM * WT_PITCH];      // W^T: [col][k], padded
    __shared__ float4 hs4[8][4 * 32];             // 16 KB staging

    {   // integrated zeroing
        const int tid = blockIdx.x * blockDim.x + threadIdx.x;
        const int gs  = gridDim.x * blockDim.x;
        float4 z4 = make_float4(0.f, 0.f, 0.f, 0.f);
        float4* hacc4 = reinterpret_cast<float4*>(g_hacc);
        const int total4 = n * (OUT_DIM / 4);
        for (int i = tid; i < total4; i += gs) hacc4[i] = z4;
        for (int i = tid; i < n; i += gs) g_esum[i] = 0.0f;
        if (tid < 2 * OUT_DIM) g_stats[tid] = 0.0f;
    }

    for (int i = threadIdx.x; i < IN_DIM * OUT_DIM; i += blockDim.x) {
        const int k = i >> 5;          // 0..127
        const int c = i & 31;          // 0..31
        Wt[c * WT_PITCH + k] = Wfc[i]; // Wfc is [k][c] row-major
    }
    __syncthreads();

    const int lane = threadIdx.x & 31;
    const int wid  = threadIdx.x >> 5;
    const int gw   = (blockIdx.x * blockDim.x + threadIdx.x) >> 5;
    const int nw   = (gridDim.x * blockDim.x) >> 5;

    const float al = Wa[lane];
    const float ar = Wa[OUT_DIM + lane];
    float4* hsw = hs4[wid];
    const float* wrow = Wt + lane * WT_PITCH;

    const int ngroups = (n + 3) >> 2;
    for (int g = gw; g < ngroups; g += nw) {
        const int base = g * 4;
        #pragma unroll
        for (int i = 0; i < 4; i++) {
            int node = base + i;
            if (node < n)
                hsw[i * 32 + lane] =
                    reinterpret_cast<const float4*>(h + (size_t)node * IN_DIM)[lane];
        }
        __syncwarp();

        float acc0 = 0.f, acc1 = 0.f, acc2 = 0.f, acc3 = 0.f;
        #pragma unroll 8
        for (int k4 = 0; k4 < 32; k4++) {
            const float4 w = *reinterpret_cast<const float4*>(wrow + k4 * 4);
            const float4 h0 = hsw[0 * 32 + k4];
            const float4 h1 = hsw[1 * 32 + k4];
            const float4 h2 = hsw[2 * 32 + k4];
            const float4 h3 = hsw[3 * 32 + k4];
            acc0 = fmaf(h0.x, w.x, acc0); acc0 = fmaf(h0.y, w.y, acc0);
            acc0 = fmaf(h0.z, w.z, acc0); acc0 = fmaf(h0.w, w.w, acc0);
            acc1 = fmaf(h1.x, w.x, acc1); acc1 = fmaf(h1.y, w.y, acc1);
            acc1 = fmaf(h1.z, w.z, acc1); acc1 = fmaf(h1.w, w.w, acc1);
            acc2 = fmaf(h2.x, w.x, acc2); acc2 = fmaf(h2.y, w.y, acc2);
            acc2 = fmaf(h2.z, w.z, acc2); acc2 = fmaf(h2.w, w.w, acc2);
            acc3 = fmaf(h3.x, w.x, acc3); acc3 = fmaf(h3.y, w.y, acc3);
            acc3 = fmaf(h3.z, w.z, acc3); acc3 = fmaf(h3.w, w.w, acc3);
        }

        float zz[4] = {acc0, acc1, acc2, acc3};
        #pragma unroll
        for (int i = 0; i < 4; i++) {
            int node = base + i;
            if (node >= n) break;
            float z = zz[i];
            g_zh[node * OUT_DIM + lane] = __float2half_rn(z);
            float vl = z * al;
            float vr = z * ar;
            #pragma unroll
            for (int off = 16; off; off >>= 1) {
                vl += __shfl_xor_sync(0xffffffffu, vl, off);
                vr += __shfl_xor_sync(0xffffffffu, vr, off);
            }
            if (lane == 0) { g_el[node] = vl; g_er[node] = vr; }
        }
        __syncwarp();
    }
}

// ---------------------------------------------------------------------------
// K2: edge pass, 8 edges per warp (2 per lane-group, interleaved for MLP).
// 8 lanes per edge; each lane gathers 8B (4 fp16 ch) and emits one v4 fp32 RED.
// Unnormalized softmax accumulation (shift-invariance; |e| small).
// ---------------------------------------------------------------------------
__global__ void __launch_bounds__(256) k_edges(
    const int* __restrict__ src, const int* __restrict__ dst, int nedges)
{
    const int lane = threadIdx.x & 31;
    const int sub  = lane >> 3;          // edge slot 0..3
    const int q    = lane & 7;           // 4-channel quarter
    const int gw   = (blockIdx.x * blockDim.x + threadIdx.x) >> 5;
    const int nw   = (gridDim.x * blockDim.x) >> 5;

    for (int base = gw * 8; base < nedges; base += nw * 8) {
        const int e0 = base + sub;
        const int e1 = base + 4 + sub;
        const bool v0 = e0 < nedges;
        const bool v1 = e1 < nedges;

        int s0 = 0, d0 = 0, s1 = 0, d1 = 0;
        if (v0) { s0 = __ldg(&src[e0]); d0 = __ldg(&dst[e0]); }
        if (v1) { s1 = __ldg(&src[e1]); d1 = __ldg(&dst[e1]); }

        float ee0 = 0.f, ee1 = 0.f;
        if (v0) ee0 = __ldg(&g_el[s0]) + __ldg(&g_er[d0]);
        if (v1) ee1 = __ldg(&g_el[s1]) + __ldg(&g_er[d1]);
        ee0 = (ee0 >= 0.0f) ? ee0 : 0.01f * ee0;
        ee1 = (ee1 >= 0.0f) ? ee1 : 0.01f * ee1;
        const float p0 = __expf(ee0);
        const float p1 = __expf(ee1);

        float2 raw0 = make_float2(0.f, 0.f), raw1 = make_float2(0.f, 0.f);
        if (v0) raw0 = __ldg(reinterpret_cast<const float2*>(g_zh + s0 * OUT_DIM) + q);
        if (v1) raw1 = __ldg(reinterpret_cast<const float2*>(g_zh + s1 * OUT_DIM) + q);

        if (v0) {
            if (q == 0) atomicAdd(&g_esum[d0], p0);
            const __half2* hp = reinterpret_cast<const __half2*>(&raw0);
            const float2 a = __half22float2(hp[0]);
            const float2 b = __half22float2(hp[1]);
            red_add_v4(g_hacc + d0 * OUT_DIM + q * 4,
                       make_float4(p0 * a.x, p0 * a.y, p0 * b.x, p0 * b.y));
        }
        if (v1) {
            if (q == 0) atomicAdd(&g_esum[d1], p1);
            const __half2* hp = reinterpret_cast<const __half2*>(&raw1);
            const float2 a = __half22float2(hp[0]);
            const float2 b = __half22float2(hp[1]);
            red_add_v4(g_hacc + d1 * OUT_DIM + q * 4,
                       make_float4(p1 * a.x, p1 * a.y, p1 * b.x, p1 * b.y));
        }
    }
}

// ---------------------------------------------------------------------------
// K3: BN stats, warp-per-node, 2 independent node chains per iteration (ILP).
// ---------------------------------------------------------------------------
__global__ void __launch_bounds__(256) k_stats(int n)
{
    __shared__ float redbuf[2][8][32];
    const int lane = threadIdx.x & 31;
    const int wid  = threadIdx.x >> 5;
    const int gw   = (blockIdx.x * blockDim.x + threadIdx.x) >> 5;
    const int nw   = (gridDim.x * blockDim.x) >> 5;

    float s = 0.f, sq = 0.f;
    for (int nd = gw; nd < n; nd += 2 * nw) {
        const int n0 = nd;
        const int n1 = nd + nw;
        const bool v1 = n1 < n;
        const float a0 = g_hacc[n0 * OUT_DIM + lane];
        const float a1 = v1 ? g_hacc[n1 * OUT_DIM + lane] : 0.0f;
        float inv0 = 0.f, inv1 = 0.f;
        if (lane == 0) {
            const float e0 = g_esum[n0];
            const float e1 = v1 ? g_esum[n1] : 0.0f;
            inv0 = (e0 > 0.0f) ? __frcp_rn(e0) : 0.0f;
            inv1 = (e1 > 0.0f) ? __frcp_rn(e1) : 0.0f;
        }
        inv0 = __shfl_sync(0xffffffffu, inv0, 0);
        inv1 = __shfl_sync(0xffffffffu, inv1, 0);
        const float x0 = a0 * inv0;
        const float x1 = a1 * inv1;
        s += x0 + x1;
        sq = fmaf(x0, x0, sq);
        sq = fmaf(x1, x1, sq);
    }
    redbuf[0][wid][lane] = s;
    redbuf[1][wid][lane] = sq;
    __syncthreads();
    if (wid == 0) {
        float a = 0.f, b = 0.f;
        #pragma unroll
        for (int w = 0; w < 8; w++) { a += redbuf[0][w][lane]; b += redbuf[1][w][lane]; }
        atomicAdd(&g_stats[lane], a);
        atomicAdd(&g_stats[OUT_DIM + lane], b);
    }
}

// ---------------------------------------------------------------------------
// K4: normalize + BN affine + ELU; warp-per-node, 2 node chains per iter.
// ---------------------------------------------------------------------------
__global__ void __launch_bounds__(256) k_elu(float* __restrict__ out,
                                             const float* __restrict__ gamma,
                                             const float* __restrict__ beta, int n)
{
    __shared__ float sc_s[OUT_DIM], sh_s[OUT_DIM];
    if (threadIdx.x < OUT_DIM) {
        const int t = threadIdx.x;
        const float inv_n = 1.0f / (float)n;
        const float mean = g_stats[t] * inv_n;
        const float var  = g_stats[OUT_DIM + t] * inv_n - mean * mean;
        const float sc   = gamma[t] * rsqrtf(var + 1e-5f);
        sc_s[t] = sc;
        sh_s[t] = beta[t] - mean * sc;
    }
    __syncthreads();

    const int lane = threadIdx.x & 31;
    const int gw   = (blockIdx.x * blockDim.x + threadIdx.x) >> 5;
    const int nw   = (gridDim.x * blockDim.x) >> 5;
    const float sc = sc_s[lane];
    const float sh = sh_s[lane];

    for (int nd = gw; nd < n; nd += 2 * nw) {
        const int n0 = nd;
        const int n1 = nd + nw;
        const bool v1 = n1 < n;
        const float a0 = g_hacc[n0 * OUT_DIM + lane];
        const float a1 = v1 ? g_hacc[n1 * OUT_DIM + lane] : 0.0f;
        float inv0 = 0.f, inv1 = 0.f;
        if (lane == 0) {
            const float e0 = g_esum[n0];
            const float e1 = v1 ? g_esum[n1] : 0.0f;
            inv0 = (e0 > 0.0f) ? __frcp_rn(e0) : 0.0f;
            inv1 = (e1 > 0.0f) ? __frcp_rn(e1) : 0.0f;
        }
        inv0 = __shfl_sync(0xffffffffu, inv0, 0);
        inv1 = __shfl_sync(0xffffffffu, inv1, 0);
        float x0 = fmaf(a0 * inv0, sc, sh);
        x0 = (x0 > 0.0f) ? x0 : expm1f(x0);
        out[n0 * OUT_DIM + lane] = x0;
        if (v1) {
            float x1 = fmaf(a1 * inv1, sc, sh);
            x1 = (x1 > 0.0f) ? x1 : expm1f(x1);
            out[n1 * OUT_DIM + lane] = x1;
        }
    }
}

// ---------------------------------------------------------------------------
extern "C" void kernel_launch(void* const* d_in, const int* in_sizes, int n_in,
                              void* d_out, int out_size)
{
    const float* h     = (const float*)d_in[0];
    const float* Wfc   = (const float*)d_in[1];
    const float* Wa    = (const float*)d_in[2];
    const float* gamma = (const float*)d_in[3];
    const float* beta  = (const float*)d_in[4];
    const int*   src   = (const int*)d_in[5];
    const int*   dst   = (const int*)d_in[6];

    const int n      = in_sizes[0] / IN_DIM;   // 100000
    const int nedges = in_sizes[5];            // 1600000
    float* out = (float*)d_out;

    k_gemm <<<1480, 256>>>(h, Wfc, Wa, n);
    k_edges<<<4096, 256>>>(src, dst, nedges);
    k_stats<<<1024, 256>>>(n);
    k_elu  <<<1024, 256>>>(out, gamma, beta, n);
}